// round 2
// baseline (speedup 1.0000x reference)
#include <cuda_runtime.h>
#include <cstdint>

// ---------------------------------------------------------------------------
// DenseAE: out = sigmoid(relu(ksparse64(relu(X@We1+be1))@Wd1+bd1)@Wd2+bd2)
// B=4096, D=12288, HID=1024, k=64
// GEMMs use 3xTF32 split precision (hi/lo) for near-fp32 accuracy.
// ---------------------------------------------------------------------------

#define BM 128
#define BN 128
#define BK 16
#define ASTR 20    // A smem stride (BK + 4): conflict-free a-frag loads
#define BSTR 136   // B smem stride (BN + 8): conflict-free b-frag loads

// Scratch (sanctioned __device__ globals; no allocation in kernel_launch)
__device__ float g_h[4096 * 1024];
__device__ float g_d[4096 * 1024];

__device__ __forceinline__ uint32_t f2tf(float x) {
    uint32_t r;
    asm("cvt.rna.tf32.f32 %0, %1;" : "=r"(r) : "f"(x));
    return r;
}

// split x into hi (tf32) + lo (tf32 of residual)
__device__ __forceinline__ void split_tf32(float x, uint32_t& hi, uint32_t& lo) {
    hi = f2tf(x);
    float r = x - __uint_as_float(hi);   // hi is exactly representable in fp32
    lo = f2tf(r);
}

__device__ __forceinline__ void mma_tf32(float c[4], const uint32_t a[4],
                                         const uint32_t b[2]) {
    asm volatile(
        "mma.sync.aligned.m16n8k8.row.col.f32.tf32.tf32.f32 "
        "{%0,%1,%2,%3}, {%4,%5,%6,%7}, {%8,%9}, {%0,%1,%2,%3};\n"
        : "+f"(c[0]), "+f"(c[1]), "+f"(c[2]), "+f"(c[3])
        : "r"(a[0]), "r"(a[1]), "r"(a[2]), "r"(a[3]), "r"(b[0]), "r"(b[1]));
}

// ACT: 0 = relu, 1 = sigmoid
template <int ACT>
__global__ void __launch_bounds__(256)
gemm_3xtf32_kernel(const float* __restrict__ A, const float* __restrict__ B,
                   const float* __restrict__ bias, float* __restrict__ C,
                   int M, int N, int K)
{
    __shared__ uint32_t sAh[BM * ASTR];
    __shared__ uint32_t sAl[BM * ASTR];
    __shared__ uint32_t sBh[BK * BSTR];
    __shared__ uint32_t sBl[BK * BSTR];

    const int tid  = threadIdx.x;
    const int lane = tid & 31;
    const int warp = tid >> 5;
    const int wm = warp >> 1;              // 0..3 (M direction)
    const int wn = warp & 1;               // 0..1 (N direction)
    const long bm = (long)blockIdx.y * BM;
    const long bn = (long)blockIdx.x * BN;

    // ---- global-load indexing ----
    const int arow = tid >> 1;             // 0..127
    const int acol = (tid & 1) * 8;        // 0 or 8
    const float* Ag = A + (bm + arow) * (long)K + acol;
    const int brow = tid >> 4;             // 0..15
    const int bcol = (tid & 15) * 8;       // 0..120
    const float* Bg = B + (long)brow * N + bn + bcol;

    float4 ra[2], rb[2];

    auto ldg_tile = [&](int kt) {
#pragma unroll
        for (int i = 0; i < 2; i++)
            ra[i] = *(const float4*)(Ag + kt + i * 4);
#pragma unroll
        for (int i = 0; i < 2; i++)
            rb[i] = *(const float4*)(Bg + (long)kt * N + i * 4);
    };
    auto sts_tile = [&]() {
#pragma unroll
        for (int i = 0; i < 2; i++) {
            uint32_t* ph = &sAh[arow * ASTR + acol + i * 4];
            uint32_t* pl = &sAl[arow * ASTR + acol + i * 4];
            split_tf32(ra[i].x, ph[0], pl[0]);
            split_tf32(ra[i].y, ph[1], pl[1]);
            split_tf32(ra[i].z, ph[2], pl[2]);
            split_tf32(ra[i].w, ph[3], pl[3]);
        }
#pragma unroll
        for (int i = 0; i < 2; i++) {
            uint32_t* ph = &sBh[brow * BSTR + bcol + i * 4];
            uint32_t* pl = &sBl[brow * BSTR + bcol + i * 4];
            split_tf32(rb[i].x, ph[0], pl[0]);
            split_tf32(rb[i].y, ph[1], pl[1]);
            split_tf32(rb[i].z, ph[2], pl[2]);
            split_tf32(rb[i].w, ph[3], pl[3]);
        }
    };

    float acc[2][8][4];
#pragma unroll
    for (int mi = 0; mi < 2; mi++)
#pragma unroll
        for (int ni = 0; ni < 8; ni++)
#pragma unroll
            for (int j = 0; j < 4; j++) acc[mi][ni][j] = 0.0f;

    const int r4 = lane >> 2;   // 0..7
    const int c4 = lane & 3;    // 0..3

    auto compute = [&]() {
#pragma unroll
        for (int ks = 0; ks < 2; ks++) {
            const int k0 = ks * 8;
            uint32_t afh[2][4], afl[2][4];
#pragma unroll
            for (int mi = 0; mi < 2; mi++) {
                const int r = wm * 32 + mi * 16 + r4;
                const int o0 = r * ASTR + k0 + c4;
                const int o1 = (r + 8) * ASTR + k0 + c4;
                afh[mi][0] = sAh[o0];     afl[mi][0] = sAl[o0];
                afh[mi][1] = sAh[o1];     afl[mi][1] = sAl[o1];
                afh[mi][2] = sAh[o0 + 4]; afl[mi][2] = sAl[o0 + 4];
                afh[mi][3] = sAh[o1 + 4]; afl[mi][3] = sAl[o1 + 4];
            }
            uint32_t bfh[8][2], bfl[8][2];
#pragma unroll
            for (int ni = 0; ni < 8; ni++) {
                const int c = wn * 64 + ni * 8 + r4;
                const int o0 = (k0 + c4) * BSTR + c;
                const int o1 = (k0 + c4 + 4) * BSTR + c;
                bfh[ni][0] = sBh[o0];  bfl[ni][0] = sBl[o0];
                bfh[ni][1] = sBh[o1];  bfl[ni][1] = sBl[o1];
            }
#pragma unroll
            for (int mi = 0; mi < 2; mi++)
#pragma unroll
                for (int ni = 0; ni < 8; ni++) {
                    mma_tf32(acc[mi][ni], afh[mi], bfl[ni]);  // hi*lo
                    mma_tf32(acc[mi][ni], afl[mi], bfh[ni]);  // lo*hi
                    mma_tf32(acc[mi][ni], afh[mi], bfh[ni]);  // hi*hi
                }
        }
    };

    ldg_tile(0);
    sts_tile();
    __syncthreads();

    for (int kt = BK; kt < K; kt += BK) {
        ldg_tile(kt);          // prefetch next tile to registers
        compute();             // consume current smem tile
        __syncthreads();
        sts_tile();
        __syncthreads();
    }
    compute();

    // ---- epilogue: bias + activation, float2 stores ----
#pragma unroll
    for (int mi = 0; mi < 2; mi++) {
        const long r = bm + wm * 32 + mi * 16 + r4;
#pragma unroll
        for (int ni = 0; ni < 8; ni++) {
            const long c = bn + wn * 64 + ni * 8 + c4 * 2;
            const float b0 = bias[c], b1 = bias[c + 1];
            float x0 = acc[mi][ni][0] + b0;
            float x1 = acc[mi][ni][1] + b1;
            float x2 = acc[mi][ni][2] + b0;
            float x3 = acc[mi][ni][3] + b1;
            if (ACT == 0) {
                x0 = fmaxf(x0, 0.f); x1 = fmaxf(x1, 0.f);
                x2 = fmaxf(x2, 0.f); x3 = fmaxf(x3, 0.f);
            } else {
                x0 = 1.f / (1.f + __expf(-x0));
                x1 = 1.f / (1.f + __expf(-x1));
                x2 = 1.f / (1.f + __expf(-x2));
                x3 = 1.f / (1.f + __expf(-x3));
            }
            float2 v0 = make_float2(x0, x1);
            float2 v1 = make_float2(x2, x3);
            *(float2*)&C[r * N + c]       = v0;
            *(float2*)&C[(r + 8) * N + c] = v1;
        }
    }
}

// ---------------------------------------------------------------------------
// Exact per-row top-64 keep (radix select over nonneg floats, in place).
// One block per row; values >= 0 so uint bit order == float order.
// ---------------------------------------------------------------------------
__global__ void __launch_bounds__(256)
topk64_kernel(float* __restrict__ h)
{
    __shared__ float vals[1024];
    __shared__ int hist[256];
    __shared__ int s_k;
    __shared__ unsigned s_prefix;

    float* row = h + (long)blockIdx.x * 1024;
    const int tid = threadIdx.x;

#pragma unroll
    for (int i = tid; i < 1024; i += 256) vals[i] = row[i];
    if (tid == 0) { s_k = 64; s_prefix = 0u; }
    __syncthreads();

#pragma unroll
    for (int shift = 24; shift >= 0; shift -= 8) {
        hist[tid] = 0;
        __syncthreads();
        const unsigned hmask = (shift == 24) ? 0u : (0xFFFFFFFFu << (shift + 8));
        const unsigned pfx = s_prefix;
#pragma unroll
        for (int i = tid; i < 1024; i += 256) {
            const unsigned u = __float_as_uint(vals[i]);
            if ((u & hmask) == pfx)
                atomicAdd(&hist[(u >> shift) & 255], 1);
        }
        __syncthreads();
        if (tid == 0) {
            int k = s_k, cum = 0, d;
            for (d = 255; d > 0; d--) {
                const int c = hist[d];
                if (cum + c >= k) break;
                cum += c;
            }
            s_prefix = pfx | ((unsigned)d << shift);
            s_k = k - cum;
        }
        __syncthreads();
    }

    const float thr = __uint_as_float(s_prefix);
#pragma unroll
    for (int i = tid; i < 1024; i += 256) {
        const float v = vals[i];
        row[i] = (v >= thr) ? v : 0.0f;
    }
}

// ---------------------------------------------------------------------------
extern "C" void kernel_launch(void* const* d_in, const int* in_sizes, int n_in,
                              void* d_out, int out_size)
{
    const float* X   = (const float*)d_in[0];   // [4096, 12288]
    const float* We1 = (const float*)d_in[1];   // [12288, 1024]
    const float* be1 = (const float*)d_in[2];   // [1024]
    const float* Wd1 = (const float*)d_in[3];   // [1024, 1024]
    const float* bd1 = (const float*)d_in[4];   // [1024]
    const float* Wd2 = (const float*)d_in[5];   // [1024, 12288]
    const float* bd2 = (const float*)d_in[6];   // [12288]
    float* out = (float*)d_out;                 // [4096, 12288]

    float *h, *d;
    cudaGetSymbolAddress((void**)&h, g_h);
    cudaGetSymbolAddress((void**)&d, g_d);

    const int M = 4096, HID = 1024, D = 12288;
    dim3 blk(256);

    // Layer 1: h = relu(X @ We1 + be1)
    gemm_3xtf32_kernel<0><<<dim3(HID / BN, M / BM), blk>>>(X, We1, be1, h, M, HID, D);
    // k-sparse (exact top-64 per row, in place)
    topk64_kernel<<<M, 256>>>(h);
    // Layer 2: d = relu(h @ Wd1 + bd1)
    gemm_3xtf32_kernel<0><<<dim3(HID / BN, M / BM), blk>>>(h, Wd1, bd1, d, M, HID, HID);
    // Layer 3: out = sigmoid(d @ Wd2 + bd2)
    gemm_3xtf32_kernel<1><<<dim3(D / BN, M / BM), blk>>>(d, Wd2, bd2, out, M, D, HID);
}

// round 4
// speedup vs baseline: 3.1640x; 3.1640x over previous
#include <cuda_runtime.h>
#include <cuda_fp16.h>
#include <cstdint>

// ===========================================================================
// DenseAE: out = sigmoid(relu(ksparse64(relu(X@We1+be1))@Wd1+bd1)@Wd2+bd2)
// B=4096, D=12288, HID=1024, k=64
// GEMMs: double-fp16 split (hi/lo) mma.m16n8k16 + ldmatrix + cp.async.
// Baseline ISA only (harness ptxas targets plain sm_100; no tcgen05).
// ===========================================================================

#define BM 128
#define BN 128
#define BK 64
#define STAGES 3
#define STAGE_BYTES 65536
#define OFF_AH 0
#define OFF_AL 16384
#define OFF_BH 32768
#define OFF_BL 49152
#define SMEM_ALLOC (STAGES * STAGE_BYTES + 1024)

// ---------------- scratch (device globals; no runtime allocation) ----------
__device__ __half g_Xh[4096L * 12288];
__device__ __half g_Xl[4096L * 12288];
__device__ __half g_W1h[1024L * 12288];   // We1^T [1024, 12288]
__device__ __half g_W1l[1024L * 12288];
__device__ __half g_W2h[1024L * 1024];    // Wd1^T [1024, 1024]
__device__ __half g_W2l[1024L * 1024];
__device__ __half g_W3h[12288L * 1024];   // Wd2^T [12288, 1024]
__device__ __half g_W3l[12288L * 1024];
__device__ float  g_h [4096L * 1024];
__device__ __half g_hh[4096L * 1024];
__device__ __half g_hl[4096L * 1024];
__device__ __half g_dh[4096L * 1024];
__device__ __half g_dl[4096L * 1024];

// ---------------- helpers ---------------------------------------------------
__device__ __forceinline__ uint32_t smem_u32(const void* p) {
    uint32_t a;
    asm("{ .reg .u64 t; cvta.to.shared.u64 t, %1; cvt.u32.u64 %0, t; }" : "=r"(a) : "l"(p));
    return a;
}
__device__ __forceinline__ void cpasync16(uint32_t dst, const void* src) {
    asm volatile("cp.async.cg.shared.global [%0], [%1], 16;" :: "r"(dst), "l"(src));
}
#define CP_COMMIT() asm volatile("cp.async.commit_group;")
#define CP_WAIT2()  asm volatile("cp.async.wait_group 2;")

__device__ __forceinline__ void ldsm4(uint32_t& r0, uint32_t& r1, uint32_t& r2,
                                      uint32_t& r3, uint32_t a) {
    asm volatile("ldmatrix.sync.aligned.m8n8.x4.shared.b16 {%0,%1,%2,%3}, [%4];"
                 : "=r"(r0), "=r"(r1), "=r"(r2), "=r"(r3) : "r"(a));
}
__device__ __forceinline__ void mma_f16(float c[4], const uint32_t a[4],
                                        const uint32_t b[2]) {
    asm volatile(
        "mma.sync.aligned.m16n8k16.row.col.f32.f16.f16.f32 "
        "{%0,%1,%2,%3}, {%4,%5,%6,%7}, {%8,%9}, {%0,%1,%2,%3};\n"
        : "+f"(c[0]), "+f"(c[1]), "+f"(c[2]), "+f"(c[3])
        : "r"(a[0]), "r"(a[1]), "r"(a[2]), "r"(a[3]), "r"(b[0]), "r"(b[1]));
}
__device__ __forceinline__ void split_h(float x, __half& hi, __half& lo) {
    hi = __float2half_rn(x);
    lo = __float2half_rn(x - __half2float(hi));   // Sterbenz-exact residual
}

// ===========================================================================
// GEMM: C[M,N] = act(A[M,K] @ Bt[N,K]^T + bias); A,Bt given as fp16 hi/lo.
// ACT: 0 relu, 1 sigmoid.  OUT_SPLIT: write fp16 (hi,lo) pair instead of f32.
// ===========================================================================
template <int ACT, int OUT_SPLIT>
__global__ void __launch_bounds__(256, 1)
gemm_fp16x2(const __half* __restrict__ Ah, const __half* __restrict__ Al,
            const __half* __restrict__ Bh, const __half* __restrict__ Bl,
            const float* __restrict__ bias, float* __restrict__ C0,
            __half* __restrict__ Sh, __half* __restrict__ Sl,
            int M, int N, int K)
{
    extern __shared__ char smem_raw[];
    const uint32_t sbase = (smem_u32(smem_raw) + 1023u) & ~1023u;
    const int tid = threadIdx.x, lane = tid & 31, warp = tid >> 5;
    const int wm = warp >> 1;            // 0..3 : M tiles of 32
    const int wn = warp & 1;             // 0..1 : N tiles of 64
    const long bm = (long)blockIdx.y * BM;
    const long bn = (long)blockIdx.x * BN;
    const int NC = K / BK;

    // ---- async stage loader: 16 cp.async x 16B per thread = 64KB ----
    auto load_stage = [&](int c) {
        const uint32_t st = sbase + (c % STAGES) * STAGE_BYTES;
        const long kt = (long)c * BK;
#pragma unroll
        for (int it = 0; it < 4; it++) {
            const int idx = tid + it * 256;
            const int row = idx >> 3, ch = idx & 7;
            const uint32_t so = (uint32_t)(row * 128 + ((ch ^ (row & 7)) << 4));
            const long goA = (bm + row) * (long)K + kt + ch * 8;
            const long goB = (bn + row) * (long)K + kt + ch * 8;
            cpasync16(st + OFF_AH + so, Ah + goA);
            cpasync16(st + OFF_AL + so, Al + goA);
            cpasync16(st + OFF_BH + so, Bh + goB);
            cpasync16(st + OFF_BL + so, Bl + goB);
        }
        CP_COMMIT();
    };

    // ---- ldmatrix lane geometry ----
    const int agrp = lane >> 3, aw = lane & 7;
    const int a_row = wm * 32 + (agrp & 1) * 8 + aw;   // + mi*16
    const int a_kc  = agrp >> 1;                       // chunk LSB
    const int b_row = wn * 64 + ((lane >> 3) >> 1) * 8 + (lane & 7); // + nj*16
    const int b_kc  = (lane >> 3) & 1;

    float acc[2][8][4];
#pragma unroll
    for (int mi = 0; mi < 2; mi++)
#pragma unroll
        for (int ni = 0; ni < 8; ni++)
#pragma unroll
            for (int j = 0; j < 4; j++) acc[mi][ni][j] = 0.0f;

    auto compute = [&](int c) {
        const uint32_t st = sbase + (c % STAGES) * STAGE_BYTES;
#pragma unroll
        for (int kk = 0; kk < 4; kk++) {
            uint32_t ah[2][4], al[2][4];
#pragma unroll
            for (int mi = 0; mi < 2; mi++) {
                const int r = a_row + mi * 16;
                const uint32_t o = (uint32_t)(r * 128 +
                    (((kk * 2 + a_kc) ^ (r & 7)) << 4));
                ldsm4(ah[mi][0], ah[mi][1], ah[mi][2], ah[mi][3], st + OFF_AH + o);
                ldsm4(al[mi][0], al[mi][1], al[mi][2], al[mi][3], st + OFF_AL + o);
            }
            uint32_t bh[8][2], bl[8][2];
#pragma unroll
            for (int nj = 0; nj < 4; nj++) {
                const int r = b_row + nj * 16;
                const uint32_t o = (uint32_t)(r * 128 +
                    (((kk * 2 + b_kc) ^ (r & 7)) << 4));
                ldsm4(bh[2 * nj][0], bh[2 * nj][1], bh[2 * nj + 1][0],
                      bh[2 * nj + 1][1], st + OFF_BH + o);
                ldsm4(bl[2 * nj][0], bl[2 * nj][1], bl[2 * nj + 1][0],
                      bl[2 * nj + 1][1], st + OFF_BL + o);
            }
#pragma unroll
            for (int mi = 0; mi < 2; mi++)
#pragma unroll
                for (int ni = 0; ni < 8; ni++) {
                    mma_f16(acc[mi][ni], ah[mi], bh[ni]);   // hi*hi
                    mma_f16(acc[mi][ni], ah[mi], bl[ni]);   // hi*lo
                    mma_f16(acc[mi][ni], al[mi], bh[ni]);   // lo*hi
                }
        }
    };

    load_stage(0); load_stage(1); load_stage(2);

    for (int c = 0; c < NC; c++) {
        CP_WAIT2();
        __syncthreads();
        compute(c);
        if (c + STAGES < NC) {
            __syncthreads();
            load_stage(c + STAGES);
        }
    }

    // ---- epilogue ----
    const int l4 = lane >> 2, l2 = (lane & 3) * 2;
#pragma unroll
    for (int mi = 0; mi < 2; mi++) {
        const long rg = bm + wm * 32 + mi * 16 + l4;
#pragma unroll
        for (int ni = 0; ni < 8; ni++) {
            const long cg = bn + wn * 64 + ni * 8 + l2;
            const float b0 = bias[cg], b1 = bias[cg + 1];
            float x0 = acc[mi][ni][0] + b0;
            float x1 = acc[mi][ni][1] + b1;
            float x2 = acc[mi][ni][2] + b0;
            float x3 = acc[mi][ni][3] + b1;
            if (ACT == 0) {
                x0 = fmaxf(x0, 0.f); x1 = fmaxf(x1, 0.f);
                x2 = fmaxf(x2, 0.f); x3 = fmaxf(x3, 0.f);
            } else {
                x0 = 1.f / (1.f + __expf(-x0));
                x1 = 1.f / (1.f + __expf(-x1));
                x2 = 1.f / (1.f + __expf(-x2));
                x3 = 1.f / (1.f + __expf(-x3));
            }
            const long o0 = rg * (long)N + cg;
            const long o1 = (rg + 8) * (long)N + cg;
            if (OUT_SPLIT) {
                __half h0, l0, h1, l1;
                split_h(x0, h0, l0); split_h(x1, h1, l1);
                *(__half2*)&Sh[o0] = __halves2half2(h0, h1);
                *(__half2*)&Sl[o0] = __halves2half2(l0, l1);
                split_h(x2, h0, l0); split_h(x3, h1, l1);
                *(__half2*)&Sh[o1] = __halves2half2(h0, h1);
                *(__half2*)&Sl[o1] = __halves2half2(l0, l1);
            } else {
                *(float2*)&C0[o0] = make_float2(x0, x1);
                *(float2*)&C0[o1] = make_float2(x2, x3);
            }
        }
    }
}

// ===========================================================================
// X [M,K] fp32 -> (hi, lo) fp16 arrays (vectorized, grid-stride)
// ===========================================================================
__global__ void __launch_bounds__(256)
split_kernel(const float* __restrict__ x, __half* __restrict__ hi,
             __half* __restrict__ lo, long n4)
{
    const long stride = (long)gridDim.x * 256;
    for (long i = blockIdx.x * 256L + threadIdx.x; i < n4; i += stride) {
        float4 v = ((const float4*)x)[i];
        __half h0, l0, h1, l1, h2, l2, h3, l3;
        split_h(v.x, h0, l0); split_h(v.y, h1, l1);
        split_h(v.z, h2, l2); split_h(v.w, h3, l3);
        ((__half2*)hi)[2 * i]     = __halves2half2(h0, h1);
        ((__half2*)hi)[2 * i + 1] = __halves2half2(h2, h3);
        ((__half2*)lo)[2 * i]     = __halves2half2(l0, l1);
        ((__half2*)lo)[2 * i + 1] = __halves2half2(l2, l3);
    }
}

// ===========================================================================
// W [K,N] fp32 -> Wt hi/lo [N,K] fp16 (transpose + split), 32x32 tiles
// ===========================================================================
__global__ void __launch_bounds__(256)
transpose_split_kernel(const float* __restrict__ W, __half* __restrict__ Wth,
                       __half* __restrict__ Wtl, int K, int N)
{
    __shared__ float t[32][33];
    const int tx = threadIdx.x, ty = threadIdx.y;
    const long n0 = (long)blockIdx.x * 32, k0 = (long)blockIdx.y * 32;
#pragma unroll
    for (int j = 0; j < 4; j++)
        t[ty + 8 * j][tx] = W[(k0 + ty + 8 * j) * N + n0 + tx];
    __syncthreads();
#pragma unroll
    for (int j = 0; j < 4; j++) {
        const float v = t[tx][ty + 8 * j];
        __half h, l;
        split_h(v, h, l);
        const long o = (n0 + ty + 8 * j) * K + k0 + tx;
        Wth[o] = h;
        Wtl[o] = l;
    }
}

// ===========================================================================
// Exact per-row top-64 keep (radix select, nonneg) + fp16 hi/lo split output
// ===========================================================================
__global__ void __launch_bounds__(256)
topk64_split_kernel(const float* __restrict__ h, __half* __restrict__ hhi,
                    __half* __restrict__ hlo)
{
    __shared__ float vals[1024];
    __shared__ int hist[256];
    __shared__ int s_k;
    __shared__ unsigned s_prefix;

    const float* row = h + (long)blockIdx.x * 1024;
    const int tid = threadIdx.x;

#pragma unroll
    for (int i = tid; i < 1024; i += 256) vals[i] = row[i];
    if (tid == 0) { s_k = 64; s_prefix = 0u; }
    __syncthreads();

#pragma unroll
    for (int shift = 24; shift >= 0; shift -= 8) {
        hist[tid] = 0;
        __syncthreads();
        const unsigned hmask = (shift == 24) ? 0u : (0xFFFFFFFFu << (shift + 8));
        const unsigned pfx = s_prefix;
#pragma unroll
        for (int i = tid; i < 1024; i += 256) {
            const unsigned u = __float_as_uint(vals[i]);
            if ((u & hmask) == pfx)
                atomicAdd(&hist[(u >> shift) & 255], 1);
        }
        __syncthreads();
        if (tid == 0) {
            int k = s_k, cum = 0, d;
            for (d = 255; d > 0; d--) {
                const int c = hist[d];
                if (cum + c >= k) break;
                cum += c;
            }
            s_prefix = pfx | ((unsigned)d << shift);
            s_k = k - cum;
        }
        __syncthreads();
    }

    const float thr = __uint_as_float(s_prefix);
    const long base = (long)blockIdx.x * 1024;
#pragma unroll
    for (int i = tid; i < 1024; i += 256) {
        const float v = vals[i];
        const float kept = (v >= thr) ? v : 0.0f;
        __half hi, lo;
        split_h(kept, hi, lo);
        hhi[base + i] = hi;
        hlo[base + i] = lo;
    }
}

// ===========================================================================
extern "C" void kernel_launch(void* const* d_in, const int* in_sizes, int n_in,
                              void* d_out, int out_size)
{
    const float* X   = (const float*)d_in[0];   // [4096, 12288]
    const float* We1 = (const float*)d_in[1];   // [12288, 1024]
    const float* be1 = (const float*)d_in[2];
    const float* Wd1 = (const float*)d_in[3];   // [1024, 1024]
    const float* bd1 = (const float*)d_in[4];
    const float* Wd2 = (const float*)d_in[5];   // [1024, 12288]
    const float* bd2 = (const float*)d_in[6];
    float* out = (float*)d_out;                 // [4096, 12288]

    __half *Xh, *Xl, *W1h, *W1l, *W2h, *W2l, *W3h, *W3l, *hh, *hl, *dh, *dl;
    float* h;
    cudaGetSymbolAddress((void**)&Xh, g_Xh);   cudaGetSymbolAddress((void**)&Xl, g_Xl);
    cudaGetSymbolAddress((void**)&W1h, g_W1h); cudaGetSymbolAddress((void**)&W1l, g_W1l);
    cudaGetSymbolAddress((void**)&W2h, g_W2h); cudaGetSymbolAddress((void**)&W2l, g_W2l);
    cudaGetSymbolAddress((void**)&W3h, g_W3h); cudaGetSymbolAddress((void**)&W3l, g_W3l);
    cudaGetSymbolAddress((void**)&h, g_h);
    cudaGetSymbolAddress((void**)&hh, g_hh);   cudaGetSymbolAddress((void**)&hl, g_hl);
    cudaGetSymbolAddress((void**)&dh, g_dh);   cudaGetSymbolAddress((void**)&dl, g_dl);

    cudaFuncSetAttribute(gemm_fp16x2<0, 0>, cudaFuncAttributeMaxDynamicSharedMemorySize, SMEM_ALLOC);
    cudaFuncSetAttribute(gemm_fp16x2<0, 1>, cudaFuncAttributeMaxDynamicSharedMemorySize, SMEM_ALLOC);
    cudaFuncSetAttribute(gemm_fp16x2<1, 0>, cudaFuncAttributeMaxDynamicSharedMemorySize, SMEM_ALLOC);

    const int M = 4096, HID = 1024, D = 12288;

    // ---- operand prep ----
    transpose_split_kernel<<<dim3(HID / 32, D / 32), dim3(32, 8)>>>(We1, W1h, W1l, D, HID);
    transpose_split_kernel<<<dim3(HID / 32, HID / 32), dim3(32, 8)>>>(Wd1, W2h, W2l, HID, HID);
    transpose_split_kernel<<<dim3(D / 32, HID / 32), dim3(32, 8)>>>(Wd2, W3h, W3l, HID, D);
    split_kernel<<<8192, 256>>>(X, Xh, Xl, (long)M * D / 4);

    // ---- layer 1: h = relu(X @ We1 + be1) ----
    gemm_fp16x2<0, 0><<<dim3(HID / BN, M / BM), 256, SMEM_ALLOC>>>(
        Xh, Xl, W1h, W1l, be1, h, nullptr, nullptr, M, HID, D);
    // ---- top-64 keep + split ----
    topk64_split_kernel<<<M, 256>>>(h, hh, hl);
    // ---- layer 2: d = relu(h @ Wd1 + bd1), output pre-split ----
    gemm_fp16x2<0, 1><<<dim3(HID / BN, M / BM), 256, SMEM_ALLOC>>>(
        hh, hl, W2h, W2l, bd1, nullptr, dh, dl, M, HID, HID);
    // ---- layer 3: out = sigmoid(d @ Wd2 + bd2) ----
    gemm_fp16x2<1, 0><<<dim3(D / BN, M / BM), 256, SMEM_ALLOC>>>(
        dh, dl, W3h, W3l, bd2, out, nullptr, nullptr, M, D, HID);
}